// round 1
// baseline (speedup 1.0000x reference)
#include <cuda_runtime.h>
#include <math.h>

#define Hdim  1024
#define RANKK 4
#define BATCHN 128
#define TSTEPS 256

// ---------------- GEMM: C[M,N] = A[M,K] @ B[K,N], fp32 ----------------
// M = 32768, N = 1024, K = 1024. A = x (row-major), B = B (row-major), C = d_out.
#define BM 128
#define BN 128
#define BKT 16
#define TM 8
#define TN 8

__global__ __launch_bounds__(256) void gemm_xB(const float* __restrict__ A,
                                               const float* __restrict__ Bm,
                                               float* __restrict__ C,
                                               int M, int N, int K) {
    __shared__ float As[BKT][BM + 4];   // transposed A tile, padded vs STS conflicts
    __shared__ float Bs[BKT][BN];

    const int tid = threadIdx.x;
    const int bx  = blockIdx.x;   // N tile
    const int by  = blockIdx.y;   // M tile

    const float* Ablk = A + (size_t)by * BM * K;
    const float* Bblk = Bm + (size_t)bx * BN;
    float*       Cblk = C + (size_t)by * BM * N + (size_t)bx * BN;

    const int tcol = tid & 15;   // 0..15
    const int trow = tid >> 4;   // 0..15

    // A loader: 4 threads/row (float4 over BKT=16 cols), 64 rows/pass, 2 passes
    const int aRow = tid >> 2;        // 0..63
    const int aCol = (tid & 3) * 4;   // 0,4,8,12
    // B loader: 32 threads/row (float4 over 128 cols), 8 rows/pass, 2 passes
    const int bRow = tid >> 5;        // 0..7
    const int bCol = (tid & 31) * 4;

    float acc[TM][TN] = {};
    float rM[TM], rN[TN];

    for (int kt = 0; kt < K; kt += BKT) {
        #pragma unroll
        for (int i = 0; i < 2; i++) {
            int r = aRow + i * 64;
            float4 v = *(const float4*)(Ablk + (size_t)r * K + kt + aCol);
            As[aCol + 0][r] = v.x;
            As[aCol + 1][r] = v.y;
            As[aCol + 2][r] = v.z;
            As[aCol + 3][r] = v.w;
        }
        #pragma unroll
        for (int i = 0; i < 2; i++) {
            int r = bRow + i * 8;
            *(float4*)&Bs[r][bCol] = *(const float4*)(Bblk + (size_t)(kt + r) * N + bCol);
        }
        __syncthreads();

        #pragma unroll
        for (int k = 0; k < BKT; k++) {
            #pragma unroll
            for (int i = 0; i < TM; i += 4)
                *(float4*)&rM[i] = *(const float4*)&As[k][trow * TM + i];
            #pragma unroll
            for (int j = 0; j < TN; j += 4)
                *(float4*)&rN[j] = *(const float4*)&Bs[k][tcol * TN + j];
            #pragma unroll
            for (int i = 0; i < TM; i++)
                #pragma unroll
                for (int j = 0; j < TN; j++)
                    acc[i][j] = fmaf(rM[i], rN[j], acc[i][j]);
        }
        __syncthreads();
    }

    #pragma unroll
    for (int i = 0; i < TM; i++) {
        int r = trow * TM + i;
        #pragma unroll
        for (int j = 0; j < TN; j += 4)
            *(float4*)(Cblk + (size_t)r * N + tcol * TN + j) = *(float4*)&acc[i][j];
    }
}

// ---------------- Recurrence: in-place over d_out ----------------
// One CTA per batch element. 256 threads, each owns 4 contiguous h-indices.
// h_{t} = tanh(d*h_{t-1} + L @ (R @ h_{t-1}) + u_t), u_t = xB row already in d_out.

__device__ __forceinline__ float tanh_fast(float x) {
    float ax = fabsf(x);
    float e  = __expf(-2.0f * ax);           // MUFU-based, ~2 ulp
    float r  = (1.0f - e) * __frcp_rn(1.0f + e);
    return copysignf(r, x);
}

__global__ __launch_bounds__(256) void recur(const float* __restrict__ h0,
                                             const float* __restrict__ dvec,
                                             const float* __restrict__ L,
                                             const float* __restrict__ R,
                                             float* __restrict__ out) {
    const int b    = blockIdx.x;
    const int tid  = threadIdx.x;
    const int warp = tid >> 5;
    const int lane = tid & 31;
    const int h    = tid * 4;

    __shared__ float4 part[2][8];   // [t parity][warp] -> rank-4 partial sums

    float4 hs = *(const float4*)(h0 + (size_t)b * Hdim + h);
    float4 dr = *(const float4*)(dvec + h);

    // L[h+i][r], r=0..3 contiguous (row-major [H, RANK])
    float4 L0 = *(const float4*)(L + (size_t)(h + 0) * RANKK);
    float4 L1 = *(const float4*)(L + (size_t)(h + 1) * RANKK);
    float4 L2 = *(const float4*)(L + (size_t)(h + 2) * RANKK);
    float4 L3 = *(const float4*)(L + (size_t)(h + 3) * RANKK);
    // R[r][h..h+3] contiguous (row-major [RANK, H])
    float4 R0 = *(const float4*)(R + 0 * Hdim + h);
    float4 R1 = *(const float4*)(R + 1 * Hdim + h);
    float4 R2 = *(const float4*)(R + 2 * Hdim + h);
    float4 R3 = *(const float4*)(R + 3 * Hdim + h);

    float* row = out + (size_t)b * TSTEPS * Hdim;

    float4 u = *(const float4*)(row + h);   // u_0
    for (int t = 0; t < TSTEPS; t++) {
        float4 u_next = make_float4(0.f, 0.f, 0.f, 0.f);
        if (t + 1 < TSTEPS)
            u_next = *(const float4*)(row + (size_t)(t + 1) * Hdim + h);  // prefetch

        // rank partials over this thread's 4 h-values
        float p0 = R0.x * hs.x + R0.y * hs.y + R0.z * hs.z + R0.w * hs.w;
        float p1 = R1.x * hs.x + R1.y * hs.y + R1.z * hs.z + R1.w * hs.w;
        float p2 = R2.x * hs.x + R2.y * hs.y + R2.z * hs.z + R2.w * hs.w;
        float p3 = R3.x * hs.x + R3.y * hs.y + R3.z * hs.z + R3.w * hs.w;

        #pragma unroll
        for (int off = 16; off >= 1; off >>= 1) {
            p0 += __shfl_xor_sync(0xFFFFFFFFu, p0, off);
            p1 += __shfl_xor_sync(0xFFFFFFFFu, p1, off);
            p2 += __shfl_xor_sync(0xFFFFFFFFu, p2, off);
            p3 += __shfl_xor_sync(0xFFFFFFFFu, p3, off);
        }
        if (lane == 0) part[t & 1][warp] = make_float4(p0, p1, p2, p3);
        __syncthreads();

        float v0 = 0.f, v1 = 0.f, v2 = 0.f, v3 = 0.f;
        #pragma unroll
        for (int w = 0; w < 8; w++) {
            float4 pw = part[t & 1][w];
            v0 += pw.x; v1 += pw.y; v2 += pw.z; v3 += pw.w;
        }

        float a0 = fmaf(dr.x, hs.x, u.x);
        float a1 = fmaf(dr.y, hs.y, u.y);
        float a2 = fmaf(dr.z, hs.z, u.z);
        float a3 = fmaf(dr.w, hs.w, u.w);
        a0 = fmaf(L0.x, v0, fmaf(L0.y, v1, fmaf(L0.z, v2, fmaf(L0.w, v3, a0))));
        a1 = fmaf(L1.x, v0, fmaf(L1.y, v1, fmaf(L1.z, v2, fmaf(L1.w, v3, a1))));
        a2 = fmaf(L2.x, v0, fmaf(L2.y, v1, fmaf(L2.z, v2, fmaf(L2.w, v3, a2))));
        a3 = fmaf(L3.x, v0, fmaf(L3.y, v1, fmaf(L3.z, v2, fmaf(L3.w, v3, a3))));

        hs.x = tanh_fast(a0);
        hs.y = tanh_fast(a1);
        hs.z = tanh_fast(a2);
        hs.w = tanh_fast(a3);

        *(float4*)(row + (size_t)t * Hdim + h) = hs;   // in-place: h_t replaces u_t
        u = u_next;
    }
}

// ---------------- launch ----------------
extern "C" void kernel_launch(void* const* d_in, const int* in_sizes, int n_in,
                              void* d_out, int out_size) {
    const float* x  = (const float*)d_in[0];
    const float* h0 = (const float*)d_in[1];
    const float* d  = (const float*)d_in[2];
    const float* L  = (const float*)d_in[3];
    const float* R  = (const float*)d_in[4];
    const float* B  = (const float*)d_in[5];
    float* out = (float*)d_out;

    const int M = BATCHN * TSTEPS;   // 32768
    dim3 grid(Hdim / BN, M / BM);    // (8, 256)
    gemm_xB<<<grid, 256>>>(x, B, out, M, Hdim, Hdim);
    recur<<<BATCHN, 256>>>(h0, d, L, R, out);
}

// round 6
// speedup vs baseline: 2.1979x; 2.1979x over previous
#include <cuda_runtime.h>
#include <cuda_bf16.h>
#include <cstdint>
#include <math.h>

#define Hdim   1024
#define RANKK  4
#define BATCHN 128
#define TSTEPS 256
#define MTOT   (BATCHN * TSTEPS)      // 32768

// ======================= helpers =======================
__device__ __forceinline__ uint32_t smem_u32(const void* p) {
    uint32_t a;
    asm("{ .reg .u64 t; cvta.to.shared.u64 t, %1; cvt.u32.u64 %0, t; }" : "=r"(a) : "l"(p));
    return a;
}
__device__ __forceinline__ void cp16(uint32_t dst, const void* src) {
    asm volatile("cp.async.cg.shared.global [%0], [%1], 16;" :: "r"(dst), "l"(src) : "memory");
}
#define CP_COMMIT() asm volatile("cp.async.commit_group;" ::: "memory")

__device__ __forceinline__ void ldsm4(uint32_t* r, uint32_t addr) {
    asm volatile("ldmatrix.sync.aligned.m8n8.x4.shared.b16 {%0,%1,%2,%3}, [%4];"
        : "=r"(r[0]), "=r"(r[1]), "=r"(r[2]), "=r"(r[3]) : "r"(addr));
}
__device__ __forceinline__ void ldsm4t(uint32_t* r, uint32_t addr) {
    asm volatile("ldmatrix.sync.aligned.m8n8.x4.trans.shared.b16 {%0,%1,%2,%3}, [%4];"
        : "=r"(r[0]), "=r"(r[1]), "=r"(r[2]), "=r"(r[3]) : "r"(addr));
}
__device__ __forceinline__ void mma16816(float* c, const uint32_t* a, uint32_t b0, uint32_t b1) {
    asm volatile("mma.sync.aligned.m16n8k16.row.col.f32.bf16.bf16.f32 "
        "{%0,%1,%2,%3}, {%4,%5,%6,%7}, {%8,%9}, {%0,%1,%2,%3};"
        : "+f"(c[0]), "+f"(c[1]), "+f"(c[2]), "+f"(c[3])
        : "r"(a[0]), "r"(a[1]), "r"(a[2]), "r"(a[3]), "r"(b0), "r"(b1));
}

// ======================= bf16 split scratch =======================
__device__ __align__(256) __nv_bfloat16 g_xh[(size_t)MTOT * Hdim];   // 64 MB
__device__ __align__(256) __nv_bfloat16 g_xl[(size_t)MTOT * Hdim];   // 64 MB
__device__ __align__(256) __nv_bfloat16 g_Bh[(size_t)Hdim * Hdim];   // 2 MB  [k][n] native layout
__device__ __align__(256) __nv_bfloat16 g_Bl[(size_t)Hdim * Hdim];

__global__ __launch_bounds__(256) void split_x_kernel(const float* __restrict__ x) {
    size_t i = (size_t)blockIdx.x * 256 + threadIdx.x;
    float4 v = ((const float4*)x)[i];
    union { __nv_bfloat16 b[4]; uint2 u; } Hh, Ll;
    Hh.b[0] = __float2bfloat16(v.x); Ll.b[0] = __float2bfloat16(v.x - __bfloat162float(Hh.b[0]));
    Hh.b[1] = __float2bfloat16(v.y); Ll.b[1] = __float2bfloat16(v.y - __bfloat162float(Hh.b[1]));
    Hh.b[2] = __float2bfloat16(v.z); Ll.b[2] = __float2bfloat16(v.z - __bfloat162float(Hh.b[2]));
    Hh.b[3] = __float2bfloat16(v.w); Ll.b[3] = __float2bfloat16(v.w - __bfloat162float(Hh.b[3]));
    *(uint2*)&g_xh[4 * i] = Hh.u;
    *(uint2*)&g_xl[4 * i] = Ll.u;
}

__global__ __launch_bounds__(256) void split_B_kernel(const float* __restrict__ B) {
    size_t i = (size_t)blockIdx.x * 256 + threadIdx.x;
    float4 v = ((const float4*)B)[i];
    union { __nv_bfloat16 b[4]; uint2 u; } Hh, Ll;
    Hh.b[0] = __float2bfloat16(v.x); Ll.b[0] = __float2bfloat16(v.x - __bfloat162float(Hh.b[0]));
    Hh.b[1] = __float2bfloat16(v.y); Ll.b[1] = __float2bfloat16(v.y - __bfloat162float(Hh.b[1]));
    Hh.b[2] = __float2bfloat16(v.z); Ll.b[2] = __float2bfloat16(v.z - __bfloat162float(Hh.b[2]));
    Hh.b[3] = __float2bfloat16(v.w); Ll.b[3] = __float2bfloat16(v.w - __bfloat162float(Hh.b[3]));
    *(uint2*)&g_Bh[4 * i] = Hh.u;
    *(uint2*)&g_Bl[4 * i] = Ll.u;
}

// ======================= HMMA GEMM =======================
// C[32768,1024] = xh@Bh + xh@Bl + xl@Bh (virtual K = 3*1024, chunks of 32)
#define BK     32
#define NCHNK  96                    // 3 slabs * 32 chunks
#define ASTRIDE 40                   // halves per A smem row (80 B, 16B-multiple)
#define BSTRIDE 136                  // halves per B smem row (272 B)
#define ASTG   (128 * ASTRIDE * 2)   // 10240 B per stage
#define BSTG   (BK * BSTRIDE * 2)    // 8704 B per stage
#define NSTAGE 3
#define SMEM_GEMM (NSTAGE * (ASTG + BSTG))   // 56832 B

__device__ __forceinline__ void load_chunk_g(uint32_t sA, uint32_t sB,
                                             const __nv_bfloat16* __restrict__ gA,
                                             const __nv_bfloat16* __restrict__ gB,
                                             int m0, int n0, int k0, int tid) {
    const int arow = tid >> 2, aseg = tid & 3;
    const int brow = tid >> 4, bseg = tid & 15;
    #pragma unroll
    for (int i = 0; i < 2; i++) {
        int ra = arow + i * 64;
        cp16(sA + ra * 80 + aseg * 16, gA + (size_t)(m0 + ra) * Hdim + k0 + aseg * 8);
        int rb = brow + i * 16;
        cp16(sB + rb * 272 + bseg * 16, gB + (size_t)(k0 + rb) * Hdim + n0 + bseg * 8);
    }
}

__global__ __launch_bounds__(256, 2) void gemm_mma(float* __restrict__ C) {
    extern __shared__ char smem[];
    const uint32_t sb  = smem_u32(smem);
    const uint32_t sbB = sb + NSTAGE * ASTG;
    const int tid = threadIdx.x, lane = tid & 31, wid = tid >> 5;
    const int wm = (wid >> 1) * 32;      // warp M offset (4 rows of warps)
    const int wn = (wid & 1) * 64;       // warp N offset (2 cols of warps)
    const int n0 = blockIdx.x * 128;
    const int m0 = blockIdx.y * 128;

    const __nv_bfloat16* slabA[3] = { g_xh, g_xh, g_xl };
    const __nv_bfloat16* slabB[3] = { g_Bh, g_Bl, g_Bh };

    // ldmatrix per-lane source offsets (bytes within a stage)
    const int r8 = lane & 7, g = lane >> 3;
    const int mrow = (g & 1) * 8 + r8;       // row within 16-row block
    const int kcolB = (g >> 1) * 16;         // 8-half column group, bytes
    uint32_t offA0 = (uint32_t)(wm + mrow) * 80 + kcolB;
    uint32_t offA1 = (uint32_t)(wm + 16 + mrow) * 80 + kcolB;
    uint32_t offB[4];
    #pragma unroll
    for (int ng = 0; ng < 4; ng++)
        offB[ng] = (uint32_t)mrow * 272 + (uint32_t)(wn + ng * 16) * 2 + kcolB;

    float acc[2][8][4] = {};

    // prologue: chunks 0 and 1
    load_chunk_g(sb, sbB, slabA[0], slabB[0], m0, n0, 0, tid);  CP_COMMIT();
    load_chunk_g(sb + ASTG, sbB + BSTG, slabA[0], slabB[0], m0, n0, 32, tid);  CP_COMMIT();

    for (int c = 0; c < NCHNK; c++) {
        const int s = c % NSTAGE;
        asm volatile("cp.async.wait_group 1;" ::: "memory");
        __syncthreads();

        if (c + 2 < NCHNK) {
            const int cn = c + 2, sn = cn % NSTAGE;
            load_chunk_g(sb + sn * ASTG, sbB + sn * BSTG,
                         slabA[cn >> 5], slabB[cn >> 5], m0, n0, (cn & 31) * BK, tid);
        }
        CP_COMMIT();   // one group per iteration (possibly empty) keeps wait_group counting uniform

        const uint32_t aB = sb + s * ASTG;
        const uint32_t bB = sbB + s * BSTG;
        #pragma unroll
        for (int ks = 0; ks < 2; ks++) {
            uint32_t a[2][4];
            ldsm4(a[0], aB + offA0 + ks * 32);
            ldsm4(a[1], aB + offA1 + ks * 32);
            uint32_t b[4][4];
            #pragma unroll
            for (int ng = 0; ng < 4; ng++)
                ldsm4t(b[ng], bB + offB[ng] + ks * 16 * 272);
            #pragma unroll
            for (int mt = 0; mt < 2; mt++)
                #pragma unroll
                for (int nt = 0; nt < 8; nt++)
                    mma16816(acc[mt][nt], a[mt], b[nt >> 1][(nt & 1) * 2], b[nt >> 1][(nt & 1) * 2 + 1]);
        }
    }

    // epilogue
    #pragma unroll
    for (int mt = 0; mt < 2; mt++) {
        const int row = m0 + wm + mt * 16 + (lane >> 2);
        #pragma unroll
        for (int nt = 0; nt < 8; nt++) {
            const int col = n0 + wn + nt * 8 + (lane & 3) * 2;
            *(float2*)&C[(size_t)row * Hdim + col]       = make_float2(acc[mt][nt][0], acc[mt][nt][1]);
            *(float2*)&C[(size_t)(row + 8) * Hdim + col] = make_float2(acc[mt][nt][2], acc[mt][nt][3]);
        }
    }
}

// ======================= recurrence (unchanged, proven) =======================
__device__ __forceinline__ float tanh_fast(float x) {
    float ax = fabsf(x);
    float e  = __expf(-2.0f * ax);
    float r  = (1.0f - e) * __frcp_rn(1.0f + e);
    return copysignf(r, x);
}

__global__ __launch_bounds__(256) void recur(const float* __restrict__ h0,
                                             const float* __restrict__ dvec,
                                             const float* __restrict__ L,
                                             const float* __restrict__ R,
                                             float* __restrict__ out) {
    const int b = blockIdx.x, tid = threadIdx.x;
    const int warp = tid >> 5, lane = tid & 31, h = tid * 4;
    __shared__ float4 part[2][8];

    float4 hs = *(const float4*)(h0 + (size_t)b * Hdim + h);
    float4 dr = *(const float4*)(dvec + h);
    float4 L0 = *(const float4*)(L + (size_t)(h + 0) * RANKK);
    float4 L1 = *(const float4*)(L + (size_t)(h + 1) * RANKK);
    float4 L2 = *(const float4*)(L + (size_t)(h + 2) * RANKK);
    float4 L3 = *(const float4*)(L + (size_t)(h + 3) * RANKK);
    float4 R0 = *(const float4*)(R + 0 * Hdim + h);
    float4 R1 = *(const float4*)(R + 1 * Hdim + h);
    float4 R2 = *(const float4*)(R + 2 * Hdim + h);
    float4 R3 = *(const float4*)(R + 3 * Hdim + h);

    float* row = out + (size_t)b * TSTEPS * Hdim;
    float4 u = *(const float4*)(row + h);
    for (int t = 0; t < TSTEPS; t++) {
        float4 u_next = make_float4(0.f, 0.f, 0.f, 0.f);
        if (t + 1 < TSTEPS) u_next = *(const float4*)(row + (size_t)(t + 1) * Hdim + h);

        float p0 = R0.x * hs.x + R0.y * hs.y + R0.z * hs.z + R0.w * hs.w;
        float p1 = R1.x * hs.x + R1.y * hs.y + R1.z * hs.z + R1.w * hs.w;
        float p2 = R2.x * hs.x + R2.y * hs.y + R2.z * hs.z + R2.w * hs.w;
        float p3 = R3.x * hs.x + R3.y * hs.y + R3.z * hs.z + R3.w * hs.w;
        #pragma unroll
        for (int off = 16; off >= 1; off >>= 1) {
            p0 += __shfl_xor_sync(0xFFFFFFFFu, p0, off);
            p1 += __shfl_xor_sync(0xFFFFFFFFu, p1, off);
            p2 += __shfl_xor_sync(0xFFFFFFFFu, p2, off);
            p3 += __shfl_xor_sync(0xFFFFFFFFu, p3, off);
        }
        if (lane == 0) part[t & 1][warp] = make_float4(p0, p1, p2, p3);
        __syncthreads();

        float v0 = 0.f, v1 = 0.f, v2 = 0.f, v3 = 0.f;
        #pragma unroll
        for (int w = 0; w < 8; w++) {
            float4 pw = part[t & 1][w];
            v0 += pw.x; v1 += pw.y; v2 += pw.z; v3 += pw.w;
        }
        float a0 = fmaf(dr.x, hs.x, u.x);
        float a1 = fmaf(dr.y, hs.y, u.y);
        float a2 = fmaf(dr.z, hs.z, u.z);
        float a3 = fmaf(dr.w, hs.w, u.w);
        a0 = fmaf(L0.x, v0, fmaf(L0.y, v1, fmaf(L0.z, v2, fmaf(L0.w, v3, a0))));
        a1 = fmaf(L1.x, v0, fmaf(L1.y, v1, fmaf(L1.z, v2, fmaf(L1.w, v3, a1))));
        a2 = fmaf(L2.x, v0, fmaf(L2.y, v1, fmaf(L2.z, v2, fmaf(L2.w, v3, a2))));
        a3 = fmaf(L3.x, v0, fmaf(L3.y, v1, fmaf(L3.z, v2, fmaf(L3.w, v3, a3))));
        hs.x = tanh_fast(a0); hs.y = tanh_fast(a1); hs.z = tanh_fast(a2); hs.w = tanh_fast(a3);
        *(float4*)(row + (size_t)t * Hdim + h) = hs;
        u = u_next;
    }
}

// ======================= launch =======================
extern "C" void kernel_launch(void* const* d_in, const int* in_sizes, int n_in,
                              void* d_out, int out_size) {
    const float* x  = (const float*)d_in[0];
    const float* h0 = (const float*)d_in[1];
    const float* d  = (const float*)d_in[2];
    const float* L  = (const float*)d_in[3];
    const float* R  = (const float*)d_in[4];
    const float* B  = (const float*)d_in[5];
    float* out = (float*)d_out;

    cudaFuncSetAttribute(gemm_mma, cudaFuncAttributeMaxDynamicSharedMemorySize, SMEM_GEMM);

    split_x_kernel<<<(size_t)MTOT * Hdim / 4 / 256, 256>>>(x);
    split_B_kernel<<<(size_t)Hdim * Hdim / 4 / 256, 256>>>(B);
    gemm_mma<<<dim3(Hdim / 128, MTOT / 128), 256, SMEM_GEMM>>>(out);
    recur<<<BATCHN, 256>>>(h0, d, L, R, out);
}